// round 11
// baseline (speedup 1.0000x reference)
#include <cuda_runtime.h>
#include <math.h>

// Problem constants
#define B_  2
#define W_  4096
#define R_  8
#define D_  32
#define C_  64                 // chunk length
#define NC_ (W_ / C_)          // 64 chunks
#define GRID_ (B_ * NC_)       // 128 blocks (<= 148 SMs: all co-resident)

// Scratch + flags (device globals — no allocation allowed)
__device__ float g_L[B_ * NC_ * R_ * D_];             // per-chunk local sums
__device__ __align__(16) unsigned g_flag[B_][NC_];    // epoch flags (monotone)

// ---------------------------------------------------------------------------
// Fused kernel. One block per (b, chunk). 512 threads.
//  Phase A: L_c[r,d] = gamma^63 * sum_j kg[r][j] h[j][d]   (kg = k*gamma^-j)
//  publish: fence; g_flag[b][c] = E+1  (plain release store; E = entry epoch)
//  overlap: A[i][j] = sum_r qg[i][r] kg[r][j]  (j<=i else 0)
//  wait:    poll g_flag[b][0..c) >= E+1 (point-to-point, no RMW)
//  Phase B: Sin = Horner(gamma^64, L[0..c)),
//           out[i,d] = sum_j A[i][j] h[j][d] + sum_r qg[i][r]*gamma_r*Sin[r][d]
// Grid 128 blocks x 512 thr, 1 block/SM: all co-resident -> wait is safe.
// Epoch flags are monotone across graph replays: no reset, no RMW anywhere
// except nothing — flags use plain relaxed ld/st only.
// ---------------------------------------------------------------------------
__global__ void __launch_bounds__(512, 1)
k_fused(const float* __restrict__ qin, const float* __restrict__ kin,
        const float* __restrict__ hin, const float* __restrict__ gamma,
        float* __restrict__ out)
{
    const int blk = blockIdx.x;
    const int b = blk >> 6, c = blk & 63;
    const int w0 = c * C_;
    const int t = threadIdx.x;

    __shared__ float hs  [C_][D_];
    __shared__ float kgT [R_][C_];
    __shared__ float qg  [C_][R_];
    __shared__ float A   [C_][C_ + 4];
    __shared__ float Sin [R_][D_];
    __shared__ float Pbuf[R_][D_];
    __shared__ float pwp [R_][C_ + 1];   // gamma_r^j, j=0..64
    __shared__ float pwn [R_][C_];       // gamma_r^-j
    __shared__ float gam_s[R_];

    // ---- 1. issue global loads FIRST (registers; longest latency) ----
    float4 hreg, kqreg;
    {
        const float4* h4 = (const float4*)(hin + (size_t)(b * W_ + w0) * D_);
        hreg = h4[t];
    }
    if (t < 128) {
        const float4* k4 = (const float4*)(kin + (size_t)(b * W_ + w0) * R_);
        kqreg = k4[t];
    } else if (t < 256) {
        const float4* q4 = (const float4*)(qin + (size_t)(b * W_ + w0) * R_);
        kqreg = q4[t - 128];
    }

    // entry epoch (t0 only): flags are uniform across blocks at launch start
    unsigned E = 0;
    if (t == 0) {
        asm volatile("ld.relaxed.gpu.global.u32 %0, [%1];"
                     : "=r"(E) : "l"(&g_flag[b][c]) : "memory");
    }

    // ---- 2. power tables by serial multiplication (no MUFU transcend.) ----
    // lanes 0..7: per-rank chains, hidden under DRAM latency of step 1.
    if (t < 8) {
        const float g  = gamma[t];
        gam_s[t] = g;
        const float gi = __frcp_rn(g);
        float p = 1.f, n = 1.f;
#pragma unroll
        for (int j = 0; j < C_; ++j) {
            pwp[t][j] = p;  pwn[t][j] = n;
            p *= g;  n *= gi;
        }
        pwp[t][C_] = p;                   // gamma^64
    }
    // h tile needs no scaling: store now
    ((float4*)hs)[t] = hreg;
    __syncthreads();

    // ---- 3. prescale k/q into shared via table lookups ----
    if (t < 128) {
        int j = t >> 1, r0 = (t & 1) * 4;
        kgT[r0 + 0][j] = kqreg.x * pwn[r0 + 0][j];
        kgT[r0 + 1][j] = kqreg.y * pwn[r0 + 1][j];
        kgT[r0 + 2][j] = kqreg.z * pwn[r0 + 2][j];
        kgT[r0 + 3][j] = kqreg.w * pwn[r0 + 3][j];
    } else if (t < 256) {
        int tt = t - 128;
        int i = tt >> 1, r0 = (tt & 1) * 4;
        qg[i][r0 + 0] = kqreg.x * pwp[r0 + 0][i];
        qg[i][r0 + 1] = kqreg.y * pwp[r0 + 1][i];
        qg[i][r0 + 2] = kqreg.z * pwp[r0 + 2][i];
        qg[i][r0 + 3] = kqreg.w * pwp[r0 + 3][i];
    }
    __syncthreads();

    // ---- Phase A: local decayed sums (512 threads: (half, r, d)) ----
    {
        const int d = t & 31, r = (t >> 5) & 7, half = t >> 8;
        const int j0 = half << 5;
        float a0 = 0.f, a1 = 0.f;
#pragma unroll
        for (int m = 0; m < 16; ++m) {
            a0 = fmaf(kgT[r][j0 + 2 * m],     hs[j0 + 2 * m][d],     a0);
            a1 = fmaf(kgT[r][j0 + 2 * m + 1], hs[j0 + 2 * m + 1][d], a1);
        }
        float part = a0 + a1;
        if (half == 0) Pbuf[r][d] = part;
        __syncthreads();
        if (half == 1) {
            g_L[((b * NC_ + c) * R_ + r) * D_ + d] = pwp[r][63] * (part + Pbuf[r][d]);
        }
    }
    __syncthreads();

    // ---- publish: release g_L via epoch flag (plain store, no RMW) ----
    if (t == 0) {
        __threadfence();
        asm volatile("st.relaxed.gpu.global.u32 [%0], %1;"
                     :: "l"(&g_flag[b][c]), "r"(E + 1) : "memory");
    }

    // ---- Stage 1: A matrix (independent of g_L — overlaps other blocks) ----
    {
        const int i1 = t >> 3;            // 0..63
        const int jb = t & 7;             // 0..7
        float qr[8];
#pragma unroll
        for (int r = 0; r < 8; ++r) qr[r] = qg[i1][r];
#pragma unroll
        for (int jj = 0; jj < 8; ++jj) {
            const int j = jb + jj * 8;
            float a = 0.f;
#pragma unroll
            for (int r = 0; r < 8; ++r) a = fmaf(qr[r], kgT[r][j], a);
            A[i1][j] = (j <= i1) ? a : 0.f;
        }
    }

    // ---- wait: only flags < c (point-to-point; early chunks barely wait).
    // nanosleep backoff keeps the poll from hammering the flag line in L2.
    if (t == 0 && c > 0) {
        const unsigned target = E + 1;
        const unsigned* fp = &g_flag[b][0];
        bool ok;
        for (;;) {
            ok = true;
#pragma unroll 4
            for (int i0 = 0; i0 < c; i0 += 4) {
                uint4 f;
                asm volatile("ld.relaxed.gpu.global.v4.u32 {%0,%1,%2,%3}, [%4];"
                             : "=r"(f.x), "=r"(f.y), "=r"(f.z), "=r"(f.w)
                             : "l"(fp + i0) : "memory");
                if ((int)(f.x - target) < 0) ok = false;
                if (i0 + 1 < c && (int)(f.y - target) < 0) ok = false;
                if (i0 + 2 < c && (int)(f.z - target) < 0) ok = false;
                if (i0 + 3 < c && (int)(f.w - target) < 0) ok = false;
            }
            if (ok) break;
            __nanosleep(40);
        }
        __threadfence();                  // acquire before g_L reads
    }
    __syncthreads();

    // ---- Sin: pairwise Horner over previous chunks (threads 0..255) ----
    if (t < 256 && c > 0) {
        const int r = t >> 5, d = t & 31;
        const float gC  = pwp[r][C_];     // gamma^64
        const float gC2 = gC * gC;
        const float* Lp = g_L + (size_t)b * NC_ * R_ * D_ + r * D_ + d;
        float s = 0.f;
        int cp = 0;
        if (c & 1) { s = __ldcg(Lp); cp = 1; }
#pragma unroll 4
        for (; cp < c; cp += 2) {
            float e = fmaf(gC, __ldcg(Lp + (size_t)cp * (R_ * D_)),
                               __ldcg(Lp + (size_t)(cp + 1) * (R_ * D_)));
            s = fmaf(gC2, s, e);
        }
        Sin[r][d] = s;
    } else if (t < 256) {
        Sin[t >> 5][t & 31] = 0.f;
    }
    __syncthreads();

    // ---- Stage 2: 16 warps; pair-split balanced rows, float4 A broadcasts ----
    {
        const int w = t >> 5;
        const int d = t & 31;
        const int r0 = w, r1 = 31 - w;      // rows with len <= 32
        const int r2 = 32 + w, r3 = 63 - w; // rows with len <= 64

        float acc0 = 0.f, acc1 = 0.f, acc2 = 0.f, acc3 = 0.f;

#pragma unroll
        for (int j4 = 0; j4 < 32; j4 += 4) {
            const float4 a0 = *(const float4*)&A[r0][j4];
            const float4 a1 = *(const float4*)&A[r1][j4];
            const float h0 = hs[j4 + 0][d], h1 = hs[j4 + 1][d];
            const float h2 = hs[j4 + 2][d], h3 = hs[j4 + 3][d];
            acc0 = fmaf(a0.x, h0, acc0); acc0 = fmaf(a0.y, h1, acc0);
            acc0 = fmaf(a0.z, h2, acc0); acc0 = fmaf(a0.w, h3, acc0);
            acc1 = fmaf(a1.x, h0, acc1); acc1 = fmaf(a1.y, h1, acc1);
            acc1 = fmaf(a1.z, h2, acc1); acc1 = fmaf(a1.w, h3, acc1);
        }
#pragma unroll
        for (int j4 = 0; j4 < 64; j4 += 4) {
            const float4 a2 = *(const float4*)&A[r2][j4];
            const float4 a3 = *(const float4*)&A[r3][j4];
            const float h0 = hs[j4 + 0][d], h1 = hs[j4 + 1][d];
            const float h2 = hs[j4 + 2][d], h3 = hs[j4 + 3][d];
            acc2 = fmaf(a2.x, h0, acc2); acc2 = fmaf(a2.y, h1, acc2);
            acc2 = fmaf(a2.z, h2, acc2); acc2 = fmaf(a2.w, h3, acc2);
            acc3 = fmaf(a3.x, h0, acc3); acc3 = fmaf(a3.y, h1, acc3);
            acc3 = fmaf(a3.z, h2, acc3); acc3 = fmaf(a3.w, h3, acc3);
        }

        // inter-chunk term: sum_r qg[i][r] * gamma_r * Sin[r][d]
#pragma unroll
        for (int r = 0; r < 8; ++r) {
            const float gs = gam_s[r];
            const float sv = Sin[r][d];
            acc0 = fmaf(qg[r0][r] * gs, sv, acc0);
            acc1 = fmaf(qg[r1][r] * gs, sv, acc1);
            acc2 = fmaf(qg[r2][r] * gs, sv, acc2);
            acc3 = fmaf(qg[r3][r] * gs, sv, acc3);
        }

        float* ob = out + (size_t)(b * W_ + w0) * D_ + d;
        ob[(size_t)r0 * D_] = acc0;
        ob[(size_t)r1 * D_] = acc1;
        ob[(size_t)r2 * D_] = acc2;
        ob[(size_t)r3 * D_] = acc3;
    }
    // no reset needed: epoch flags are monotone across graph replays
}

// ---------------------------------------------------------------------------
// Launch. Inputs (metadata order):
//   0: q_alpha [B,W,R]  1: k [B,W,R]  2: h_norm [B,W,D]
//   3: gamma_vec [R]    4: causal_mask (unused)  5: decay_diff (unused)
// out: float32 [B,W,D]
// ---------------------------------------------------------------------------
extern "C" void kernel_launch(void* const* d_in, const int* in_sizes, int n_in,
                              void* d_out, int out_size)
{
    const float* q     = (const float*)d_in[0];
    const float* k     = (const float*)d_in[1];
    const float* h     = (const float*)d_in[2];
    const float* gamma = (const float*)d_in[3];
    float* out         = (float*)d_out;

    k_fused<<<GRID_, 512>>>(q, k, h, gamma, out);
}